// round 13
// baseline (speedup 1.0000x reference)
#include <cuda_runtime.h>
#include <cuda_bf16.h>
#include <cstdint>

// Constants: B=16, C=128, T=8, BR=16, S=8, SY=64, INPUT_SIZE=16384, C*T*BR=16384
// seg_on = (count>=16 of 64), branch_on = (count>=4 of 8)
// Output = layer2 branch_on at t==0 -> (16,128,16) float32
//
// Dual-branch bit-slicing: every 32-bit register carries branch A's 16 batch
// bits in the low half and branch B's in the high half. One warp = one
// branch-pair; lane L owns segment L>>2, quarter L&3 (16 synapses per branch).

__device__ __align__(16) uint16_t g_xbits[16384];
__device__ __align__(16) uint16_t g_act1[16384];

__device__ __forceinline__ uint32_t maj3(uint32_t a, uint32_t b, uint32_t c) {
    return (a & b) | (a & c) | (b & c);
}

#define SHFLX(v, m) __shfl_xor_sync(0xffffffffu, (v), (m))

// Dual branch mask: lane gets 4 int4 of branch A and 4 int4 of branch B.
// Returns on ALL lanes: lo16 = branch_on batch mask of A, hi16 = of B.
__device__ __forceinline__ uint32_t branch_mask_dual(
    int4 a0, int4 a1, int4 a2, int4 a3,
    int4 e0, int4 e1, int4 e2, int4 e3,
    const uint16_t* __restrict__ sx) {
#define LK(v) ((uint32_t)sx[(v) + 8])
    uint32_t m0 = LK(a0.x) | (LK(e0.x) << 16), m1 = LK(a0.y) | (LK(e0.y) << 16);
    uint32_t m2 = LK(a0.z) | (LK(e0.z) << 16), m3 = LK(a0.w) | (LK(e0.w) << 16);
    uint32_t m4 = LK(a1.x) | (LK(e1.x) << 16), m5 = LK(a1.y) | (LK(e1.y) << 16);
    uint32_t m6 = LK(a1.z) | (LK(e1.z) << 16), m7 = LK(a1.w) | (LK(e1.w) << 16);
    uint32_t m8 = LK(a2.x) | (LK(e2.x) << 16), m9 = LK(a2.y) | (LK(e2.y) << 16);
    uint32_t mA = LK(a2.z) | (LK(e2.z) << 16), mB = LK(a2.w) | (LK(e2.w) << 16);
    uint32_t mC = LK(a3.x) | (LK(e3.x) << 16), mD = LK(a3.y) | (LK(e3.y) << 16);
    uint32_t mE = LK(a3.z) | (LK(e3.z) << 16), mF = LK(a3.w) | (LK(e3.w) << 16);
#undef LK

    // Wallace-8 #1: sum(m0..m7) = a1s + 2*a2s + 4*a4s + 8*a8s (per bit lane)
    uint32_t s1 = m0 ^ m1 ^ m2, c1 = maj3(m0, m1, m2);
    uint32_t s2 = m3 ^ m4 ^ m5, c2 = maj3(m3, m4, m5);
    uint32_t s3 = s1 ^ s2 ^ m6, c3 = maj3(s1, s2, m6);
    uint32_t a1s = s3 ^ m7,      c4 = s3 & m7;
    uint32_t s4 = c1 ^ c2 ^ c3, c5 = maj3(c1, c2, c3);
    uint32_t a2s = s4 ^ c4,      c6 = s4 & c4;
    uint32_t a4s = c5 ^ c6,      a8s = c5 & c6;
    // Wallace-8 #2: sum(m8..mF)
    uint32_t u1 = m8 ^ m9 ^ mA, e1c = maj3(m8, m9, mA);
    uint32_t u2 = mB ^ mC ^ mD, e2c = maj3(mB, mC, mD);
    uint32_t u3 = u1 ^ u2 ^ mE, e3c = maj3(u1, u2, mE);
    uint32_t b1s = u3 ^ mF,      e4c = u3 & mF;
    uint32_t u4 = e1c ^ e2c ^ e3c, e5c = maj3(e1c, e2c, e3c);
    uint32_t b2s = u4 ^ e4c,       e6c = u4 & e4c;
    uint32_t b4s = e5c ^ e6c,      b8s = e5c & e6c;

    // ripple: (<=8) + (<=8) -> <=16 in slices v0..v4
    uint32_t k  = a1s & b1s;
    uint32_t v0 = a1s ^ b1s;
    uint32_t v1 = a2s ^ b2s ^ k;  k = maj3(a2s, b2s, k);
    uint32_t v2 = a4s ^ b4s ^ k;  k = maj3(a4s, b4s, k);
    uint32_t v3 = a8s ^ b8s ^ k;
    uint32_t v4 = maj3(a8s, b8s, k);

    // merge level 1 (xor 1): <=16 + <=16 -> <=32
    uint32_t r0 = SHFLX(v0, 1), r1 = SHFLX(v1, 1), r2 = SHFLX(v2, 1),
             r3 = SHFLX(v3, 1), r4 = SHFLX(v4, 1);
    k = v0 & r0;
    uint32_t t0 = v0 ^ r0;
    uint32_t t1 = v1 ^ r1 ^ k;  k = maj3(v1, r1, k);
    uint32_t t2 = v2 ^ r2 ^ k;  k = maj3(v2, r2, k);
    uint32_t t3 = v3 ^ r3 ^ k;  k = maj3(v3, r3, k);
    uint32_t t4 = v4 ^ r4 ^ k;
    uint32_t t5 = maj3(v4, r4, k);

    // merge level 2 (xor 2): need only (sum >= 16) of (<=32 + <=32)
    r0 = SHFLX(t0, 2); r1 = SHFLX(t1, 2); r2 = SHFLX(t2, 2); r3 = SHFLX(t3, 2);
    r4 = SHFLX(t4, 2); uint32_t r5 = SHFLX(t5, 2);
    k = t0 & r0;
    k = maj3(t1, r1, k);
    k = maj3(t2, r2, k);
    k = maj3(t3, r3, k);
    uint32_t segmask = t4 | r4 | t5 | r5 | k;   // dual seg_on for lane's segment

    // branch reduction: >=4 of 8 segments via xor 4/8/16 (dual)
    uint32_t p  = SHFLX(segmask, 4);
    uint32_t c0 = segmask ^ p, cc1 = segmask & p;
    uint32_t q0 = SHFLX(c0, 8), q1 = SHFLX(cc1, 8);
    k = c0 & q0;
    uint32_t f0 = c0 ^ q0;
    uint32_t f1 = cc1 ^ q1 ^ k;
    uint32_t f2 = maj3(cc1, q1, k);
    uint32_t h0 = SHFLX(f0, 16), h1 = SHFLX(f1, 16), h2 = SHFLX(f2, 16);
    k = f0 & h0;
    uint32_t k2 = maj3(f1, h1, k);
    return f2 | h2 | k2;       // lo16 = branch A on, hi16 = branch B on
}

// Vectorized table fill: entry j -> sx[j+8]; slots 0..7 zeroed (-1 -> slot 7).
__device__ __forceinline__ void fill_table(uint16_t* sx, const uint16_t* gtab) {
    const uint4* src = reinterpret_cast<const uint4*>(gtab);   // 2048 uint4
    uint4* dst = reinterpret_cast<uint4*>(sx + 8);
    for (int i = threadIdx.x; i < 2048; i += 256) dst[i] = src[i];
    if (threadIdx.x < 8) sx[threadIdx.x] = 0;
    __syncthreads();
}

// Pack x (16 x 16384 floats of {0,1}) into per-position 16-bit batch masks.
__global__ void __launch_bounds__(256) k_pack(const float* __restrict__ x) {
    int j = blockIdx.x * 256 + threadIdx.x;
    float v[16];
#pragma unroll
    for (int b = 0; b < 16; b++) v[b] = x[b * 16384 + j];
    uint32_t m = 0;
#pragma unroll
    for (int b = 0; b < 16; b++)
        m |= (v[b] != 0.0f) ? (1u << b) : 0u;
    g_xbits[j] = (uint16_t)m;
    cudaTriggerProgrammaticLaunchCompletion();
}

// Layer 1: 1024 blocks x 8 warps; warp = one branch-PAIR (8192 pairs total).
// 8 int4 idx loads hoisted above the PDL sync (independent of k_pack).
__global__ void __launch_bounds__(256) k_layer1(const int* __restrict__ idx) {
    __shared__ __align__(16) uint16_t sx[16400];

    int w = threadIdx.x >> 5, lane = threadIdx.x & 31;
    int seg = lane >> 2, q = lane & 3;
    int pair = blockIdx.x * 8 + w;                 // 0..8191
    const int4* baseA = reinterpret_cast<const int4*>(
        idx + pair * 1024 + seg * 64 + q * 16);    // branch 2*pair
    const int4* baseB = baseA + 128;               // branch 2*pair+1 (+512 ints)

    int4 A0 = __ldcs(baseA),     A1 = __ldcs(baseA + 1);
    int4 A2 = __ldcs(baseA + 2), A3 = __ldcs(baseA + 3);
    int4 E0 = __ldcs(baseB),     E1 = __ldcs(baseB + 1);
    int4 E2 = __ldcs(baseB + 2), E3 = __ldcs(baseB + 3);

    cudaGridDependencySynchronize();      // wait for k_pack's g_xbits
    fill_table(sx, g_xbits);

    uint32_t ge4 = branch_mask_dual(A0, A1, A2, A3, E0, E1, E2, E3, sx);
    if (lane == 0)
        reinterpret_cast<uint32_t*>(g_act1)[pair] = ge4;   // lo->2*pair, hi->2*pair+1
    cudaTriggerProgrammaticLaunchCompletion();
}

// Layer 2 (t==0 only): 128 blocks x 8 warps; warp = one (c,br) branch-pair.
// Pairs are (pr, pr+1) with pr even -> same column c, br and br+1.
__global__ void __launch_bounds__(256) k_layer2(const int* __restrict__ idx,
                                                float* __restrict__ out) {
    __shared__ __align__(16) uint16_t sx[16400];

    int w = threadIdx.x >> 5, lane = threadIdx.x & 31;
    int seg = lane >> 2, q = lane & 3;
    int pr = (blockIdx.x * 8 + w) * 2;             // even branch id = c*16 + br
    int c = pr >> 4, brA = pr & 15;
    // idx2 flat offset of (c, t=0, br, seg, q*16); branch B = brA+1 -> +512 ints
    const int4* baseA = reinterpret_cast<const int4*>(
        idx + (c * 1024 + brA * 8 + seg) * 64 + q * 16);
    const int4* baseB = baseA + 128;

    int4 A0 = __ldcs(baseA),     A1 = __ldcs(baseA + 1);
    int4 A2 = __ldcs(baseA + 2), A3 = __ldcs(baseA + 3);
    int4 E0 = __ldcs(baseB),     E1 = __ldcs(baseB + 1);
    int4 E2 = __ldcs(baseB + 2), E3 = __ldcs(baseB + 3);

    cudaGridDependencySynchronize();      // wait for k_layer1's g_act1
    fill_table(sx, g_act1);

    uint32_t ge4 = branch_mask_dual(A0, A1, A2, A3, E0, E1, E2, E3, sx);

    // lanes 0..15 -> batches of branch A; lanes 16..31 -> batches of branch B
    int batch = lane & 15;
    int br = brA + (lane >> 4);
    out[(batch * 128 + c) * 16 + br] = ((ge4 >> lane) & 1u) ? 1.0f : 0.0f;
}

extern "C" void kernel_launch(void* const* d_in, const int* in_sizes, int n_in,
                              void* d_out, int out_size) {
    const float* x = nullptr;
    const int* idxA = nullptr;
    const int* idxB = nullptr;
    for (int i = 0; i < n_in; i++) {
        if (in_sizes[i] == 262144 && !x) {
            x = (const float*)d_in[i];
        } else if (!idxA) {
            idxA = (const int*)d_in[i];
        } else if (!idxB) {
            idxB = (const int*)d_in[i];
        }
    }
    if (!x) { x = (const float*)d_in[0]; idxA = (const int*)d_in[1]; idxB = (const int*)d_in[2]; }

    float* out = (float*)d_out;   // (16, 128, 16) float32

    // k_pack: normal launch (nothing upstream)
    k_pack<<<64, 256>>>(const_cast<float*>(x));

    // k_layer1 / k_layer2: programmatic dependent launch (overlap with upstream)
    cudaLaunchAttribute attr[1];
    attr[0].id = cudaLaunchAttributeProgrammaticStreamSerialization;
    attr[0].val.programmaticStreamSerializationAllowed = 1;

    {
        cudaLaunchConfig_t cfg = {};
        cfg.gridDim = dim3(1024, 1, 1);
        cfg.blockDim = dim3(256, 1, 1);
        cfg.dynamicSmemBytes = 0;
        cfg.stream = 0;
        cfg.attrs = attr;
        cfg.numAttrs = 1;
        cudaLaunchKernelEx(&cfg, k_layer1, idxA);
    }
    {
        cudaLaunchConfig_t cfg = {};
        cfg.gridDim = dim3(128, 1, 1);
        cfg.blockDim = dim3(256, 1, 1);
        cfg.dynamicSmemBytes = 0;
        cfg.stream = 0;
        cfg.attrs = attr;
        cfg.numAttrs = 1;
        cudaLaunchKernelEx(&cfg, k_layer2, idxB, (float*)d_out);
    }
}

// round 14
// speedup vs baseline: 1.1199x; 1.1199x over previous
#include <cuda_runtime.h>
#include <cuda_bf16.h>
#include <cstdint>

// Constants: B=16, C=128, T=8, BR=16, S=8, SY=64, INPUT_SIZE=16384, C*T*BR=16384
// seg_on = (count>=16 of 64), branch_on = (count>=4 of 8)
// Output = layer2 branch_on at t==0 -> (16,128,16) float32

#define NB 256   // persistent blocks; launch_bounds(256,2) guarantees 296 co-resident

__device__ __align__(16) uint16_t g_xbits[16384];
__device__ __align__(16) uint16_t g_act1[16384];
__device__ unsigned g_count = 0;
__device__ unsigned g_gen   = 0;

__device__ __forceinline__ uint32_t maj3(uint32_t a, uint32_t b, uint32_t c) {
    return (a & b) | (a & c) | (b & c);
}

#define SHFLX(v, m) __shfl_xor_sync(0xffffffffu, (v), (m))

__device__ __forceinline__ uint32_t smem_u32(const void* p) {
    uint32_t a;
    asm("{ .reg .u64 t; cvta.to.shared.u64 t, %1; cvt.u32.u64 %0, t; }"
        : "=r"(a) : "l"(p));
    return a;
}

__device__ __forceinline__ void mbar_wait(uint32_t mbar, uint32_t parity) {
    asm volatile(
        "{\n\t"
        ".reg .pred P;\n\t"
        "W_%=:\n\t"
        "mbarrier.try_wait.parity.shared::cta.b64 P, [%0], %1;\n\t"
        "@!P bra W_%=;\n\t"
        "}" :: "r"(mbar), "r"(parity) : "memory");
}

// One-shot 32KB global->shared bulk copy (TMA path; no per-thread LDG/STS).
__device__ __forceinline__ void bulk_fill(uint16_t* sx, const void* gsrc,
                                          uint32_t mbar, uint32_t parity) {
    if (threadIdx.x == 0) {
        asm volatile("mbarrier.arrive.expect_tx.shared::cta.b64 _, [%0], %1;"
                     :: "r"(mbar), "r"(32768u) : "memory");
        uint32_t dst = smem_u32(sx + 8);
        asm volatile(
            "cp.async.bulk.shared::cluster.global.mbarrier::complete_tx::bytes "
            "[%0], [%1], %2, [%3];"
            :: "r"(dst), "l"(gsrc), "r"(32768u), "r"(mbar) : "memory");
    }
    if (threadIdx.x < 8) sx[threadIdx.x] = 0;   // slots 0..7 (idx==-1 -> slot 7)
    mbar_wait(mbar, parity);
    __syncthreads();
}

// Software grid barrier (sense-reversal; self-resetting -> graph-replay-safe).
__device__ __forceinline__ void grid_barrier() {
    __threadfence();
    __syncthreads();
    if (threadIdx.x == 0) {
        unsigned gen = *(volatile unsigned*)&g_gen;
        if (atomicAdd(&g_count, 1u) == NB - 1u) {
            atomicExch(&g_count, 0u);
            __threadfence();
            atomicAdd(&g_gen, 1u);
        } else {
            while (*(volatile unsigned*)&g_gen == gen) { __nanosleep(32); }
        }
    }
    __syncthreads();
    __threadfence();
}

// Dual branch mask (proven R13): lane gets 4 int4 of branch A, 4 of branch B.
// Returns on ALL lanes: lo16 = branch_on batch mask of A, hi16 = of B.
__device__ __forceinline__ uint32_t branch_mask_dual(
    const int4* A, const int4* E, const uint16_t* __restrict__ sx) {
    int4 a0 = A[0], a1 = A[1], a2 = A[2], a3 = A[3];
    int4 e0 = E[0], e1 = E[1], e2 = E[2], e3 = E[3];
#define LK(v) ((uint32_t)sx[(v) + 8])
    uint32_t m0 = LK(a0.x) | (LK(e0.x) << 16), m1 = LK(a0.y) | (LK(e0.y) << 16);
    uint32_t m2 = LK(a0.z) | (LK(e0.z) << 16), m3 = LK(a0.w) | (LK(e0.w) << 16);
    uint32_t m4 = LK(a1.x) | (LK(e1.x) << 16), m5 = LK(a1.y) | (LK(e1.y) << 16);
    uint32_t m6 = LK(a1.z) | (LK(e1.z) << 16), m7 = LK(a1.w) | (LK(e1.w) << 16);
    uint32_t m8 = LK(a2.x) | (LK(e2.x) << 16), m9 = LK(a2.y) | (LK(e2.y) << 16);
    uint32_t mA = LK(a2.z) | (LK(e2.z) << 16), mB = LK(a2.w) | (LK(e2.w) << 16);
    uint32_t mC = LK(a3.x) | (LK(e3.x) << 16), mD = LK(a3.y) | (LK(e3.y) << 16);
    uint32_t mE = LK(a3.z) | (LK(e3.z) << 16), mF = LK(a3.w) | (LK(e3.w) << 16);
#undef LK

    uint32_t s1 = m0 ^ m1 ^ m2, c1 = maj3(m0, m1, m2);
    uint32_t s2 = m3 ^ m4 ^ m5, c2 = maj3(m3, m4, m5);
    uint32_t s3 = s1 ^ s2 ^ m6, c3 = maj3(s1, s2, m6);
    uint32_t a1s = s3 ^ m7,      c4 = s3 & m7;
    uint32_t s4 = c1 ^ c2 ^ c3, c5 = maj3(c1, c2, c3);
    uint32_t a2s = s4 ^ c4,      c6 = s4 & c4;
    uint32_t a4s = c5 ^ c6,      a8s = c5 & c6;
    uint32_t u1 = m8 ^ m9 ^ mA, e1c = maj3(m8, m9, mA);
    uint32_t u2 = mB ^ mC ^ mD, e2c = maj3(mB, mC, mD);
    uint32_t u3 = u1 ^ u2 ^ mE, e3c = maj3(u1, u2, mE);
    uint32_t b1s = u3 ^ mF,      e4c = u3 & mF;
    uint32_t u4 = e1c ^ e2c ^ e3c, e5c = maj3(e1c, e2c, e3c);
    uint32_t b2s = u4 ^ e4c,       e6c = u4 & e4c;
    uint32_t b4s = e5c ^ e6c,      b8s = e5c & e6c;

    uint32_t k  = a1s & b1s;
    uint32_t v0 = a1s ^ b1s;
    uint32_t v1 = a2s ^ b2s ^ k;  k = maj3(a2s, b2s, k);
    uint32_t v2 = a4s ^ b4s ^ k;  k = maj3(a4s, b4s, k);
    uint32_t v3 = a8s ^ b8s ^ k;
    uint32_t v4 = maj3(a8s, b8s, k);

    uint32_t r0 = SHFLX(v0, 1), r1 = SHFLX(v1, 1), r2 = SHFLX(v2, 1),
             r3 = SHFLX(v3, 1), r4 = SHFLX(v4, 1);
    k = v0 & r0;
    uint32_t t0 = v0 ^ r0;
    uint32_t t1 = v1 ^ r1 ^ k;  k = maj3(v1, r1, k);
    uint32_t t2 = v2 ^ r2 ^ k;  k = maj3(v2, r2, k);
    uint32_t t3 = v3 ^ r3 ^ k;  k = maj3(v3, r3, k);
    uint32_t t4 = v4 ^ r4 ^ k;
    uint32_t t5 = maj3(v4, r4, k);

    r0 = SHFLX(t0, 2); r1 = SHFLX(t1, 2); r2 = SHFLX(t2, 2); r3 = SHFLX(t3, 2);
    r4 = SHFLX(t4, 2); uint32_t r5 = SHFLX(t5, 2);
    k = t0 & r0;
    k = maj3(t1, r1, k);
    k = maj3(t2, r2, k);
    k = maj3(t3, r3, k);
    uint32_t segmask = t4 | r4 | t5 | r5 | k;

    uint32_t p  = SHFLX(segmask, 4);
    uint32_t c0 = segmask ^ p, cc1 = segmask & p;
    uint32_t q0 = SHFLX(c0, 8), q1 = SHFLX(cc1, 8);
    k = c0 & q0;
    uint32_t f0 = c0 ^ q0;
    uint32_t f1 = cc1 ^ q1 ^ k;
    uint32_t f2 = maj3(cc1, q1, k);
    uint32_t h0 = SHFLX(f0, 16), h1 = SHFLX(f1, 16), h2 = SHFLX(f2, 16);
    k = f0 & h0;
    uint32_t k2 = maj3(f1, h1, k);
    return f2 | h2 | k2;
}

// Pack x (16 x 16384 floats of {0,1}) into per-position 16-bit batch masks.
__global__ void __launch_bounds__(256) k_pack(const float* __restrict__ x) {
    int j = blockIdx.x * 256 + threadIdx.x;
    float v[16];
#pragma unroll
    for (int b = 0; b < 16; b++) v[b] = x[b * 16384 + j];
    uint32_t m = 0;
#pragma unroll
    for (int b = 0; b < 16; b++)
        m |= (v[b] != 0.0f) ? (1u << b) : 0u;
    g_xbits[j] = (uint16_t)m;
    cudaTriggerProgrammaticLaunchCompletion();
}

// Fused layers: 256 blocks x 8 warps.
// Layer1: warp = 4 dual-pairs (8 branches); 256*8*4 = 8192 pairs = 16384 branches.
// Layer2: blocks 0..127, warp = 1 dual-pair; 128*8 = 1024 pairs = 2048 branches.
__global__ void __launch_bounds__(256, 2) k_main(const int* __restrict__ idx1,
                                                 const int* __restrict__ idx2,
                                                 float* __restrict__ out) {
    __shared__ __align__(16) uint16_t sx[16400];
    __shared__ __align__(8) uint64_t mbar[1];

    int tid = threadIdx.x;
    int w = tid >> 5, lane = tid & 31;
    int seg = lane >> 2, q = lane & 3;
    uint32_t mb = smem_u32(mbar);

    if (tid == 0) {
        asm volatile("mbarrier.init.shared::cta.b64 [%0], 1;" :: "r"(mb) : "memory");
    }

    // ---- Layer 1 loads for pair 0 hoisted above the PDL sync ----
    int pair0 = (blockIdx.x * 8 + w) * 4;
    const int4* b0 = reinterpret_cast<const int4*>(idx1 + pair0 * 1024 + seg * 64 + q * 16);

    int4 A[4], E[4], NA[4], NE[4];
#pragma unroll
    for (int i = 0; i < 4; i++) A[i] = __ldcs(b0 + i);
#pragma unroll
    for (int i = 0; i < 4; i++) E[i] = __ldcs(b0 + 128 + i);

    cudaGridDependencySynchronize();          // upstream: k_pack
    __syncthreads();                          // mbarrier init visible
    bulk_fill(sx, g_xbits, mb, 0);            // 32KB TMA fill, parity 0

    // ---- Layer 1: 4 dual-pairs per warp, depth-1 lookahead ----
#pragma unroll
    for (int p = 0; p < 4; p++) {
        if (p < 3) {
            const int4* bn = reinterpret_cast<const int4*>(
                idx1 + (pair0 + p + 1) * 1024 + seg * 64 + q * 16);
#pragma unroll
            for (int i = 0; i < 4; i++) NA[i] = __ldcs(bn + i);
#pragma unroll
            for (int i = 0; i < 4; i++) NE[i] = __ldcs(bn + 128 + i);
        }
        uint32_t ge = branch_mask_dual(A, E, sx);
        if (lane == 0)
            reinterpret_cast<uint32_t*>(g_act1)[pair0 + p] = ge;
#pragma unroll
        for (int i = 0; i < 4; i++) { A[i] = NA[i]; E[i] = NE[i]; }
    }

    // ---- Layer 2 loads hoisted ABOVE the grid barrier (independent of act1) ----
    bool active2 = blockIdx.x < 128;
    int pr = (blockIdx.x * 8 + w) * 2;        // even branch id = c*16 + br
    int c = pr >> 4, brA = pr & 15;
    if (active2) {
        const int4* baseA = reinterpret_cast<const int4*>(
            idx2 + (c * 1024 + brA * 8 + seg) * 64 + q * 16);
#pragma unroll
        for (int i = 0; i < 4; i++) A[i] = __ldcs(baseA + i);
#pragma unroll
        for (int i = 0; i < 4; i++) E[i] = __ldcs(baseA + 128 + i);
    }

    grid_barrier();                           // all act1 written & visible

    if (!active2) return;
    bulk_fill(sx, g_act1, mb, 1);             // parity 1 (second use of mbar)

    uint32_t ge4 = branch_mask_dual(A, E, sx);
    // lanes 0..15 -> batches of branch A; 16..31 -> batches of branch B
    int batch = lane & 15;
    int br = brA + (lane >> 4);
    out[(batch * 128 + c) * 16 + br] = ((ge4 >> lane) & 1u) ? 1.0f : 0.0f;
}

extern "C" void kernel_launch(void* const* d_in, const int* in_sizes, int n_in,
                              void* d_out, int out_size) {
    const float* x = nullptr;
    const int* idxA = nullptr;
    const int* idxB = nullptr;
    for (int i = 0; i < n_in; i++) {
        if (in_sizes[i] == 262144 && !x) {
            x = (const float*)d_in[i];
        } else if (!idxA) {
            idxA = (const int*)d_in[i];
        } else if (!idxB) {
            idxB = (const int*)d_in[i];
        }
    }
    if (!x) { x = (const float*)d_in[0]; idxA = (const int*)d_in[1]; idxB = (const int*)d_in[2]; }

    float* out = (float*)d_out;   // (16, 128, 16) float32

    k_pack<<<64, 256>>>(const_cast<float*>(x));

    cudaLaunchAttribute attr[1];
    attr[0].id = cudaLaunchAttributeProgrammaticStreamSerialization;
    attr[0].val.programmaticStreamSerializationAllowed = 1;

    cudaLaunchConfig_t cfg = {};
    cfg.gridDim = dim3(NB, 1, 1);
    cfg.blockDim = dim3(256, 1, 1);
    cfg.dynamicSmemBytes = 0;
    cfg.stream = 0;
    cfg.attrs = attr;
    cfg.numAttrs = 1;
    cudaLaunchKernelEx(&cfg, k_main, idxA, idxB, out);
}

// round 15
// speedup vs baseline: 1.1218x; 1.0017x over previous
#include <cuda_runtime.h>
#include <cuda_bf16.h>
#include <cstdint>

// Constants: B=16, C=128, T=8, BR=16, S=8, SY=64, INPUT_SIZE=16384, C*T*BR=16384
// seg_on = (count>=16 of 64), branch_on = (count>=4 of 8)
// Output = layer2 branch_on at t==0 -> (16,128,16) float32

#define NB 256   // persistent blocks; launch_bounds(256,2) guarantees co-residency

__device__ __align__(16) uint16_t g_xbits[16384];
__device__ __align__(16) uint16_t g_act1[16384];
__device__ unsigned g_count = 0;
__device__ unsigned g_gen   = 0;

__device__ __forceinline__ uint32_t maj3(uint32_t a, uint32_t b, uint32_t c) {
    return (a & b) | (a & c) | (b & c);
}

#define SHFLX(v, m) __shfl_xor_sync(0xffffffffu, (v), (m))

__device__ __forceinline__ uint32_t smem_u32(const void* p) {
    uint32_t a;
    asm("{ .reg .u64 t; cvta.to.shared.u64 t, %1; cvt.u32.u64 %0, t; }"
        : "=r"(a) : "l"(p));
    return a;
}

__device__ __forceinline__ void mbar_wait(uint32_t mbar, uint32_t parity) {
    asm volatile(
        "{\n\t"
        ".reg .pred P;\n\t"
        "W_%=:\n\t"
        "mbarrier.try_wait.parity.shared::cta.b64 P, [%0], %1;\n\t"
        "@!P bra W_%=;\n\t"
        "}" :: "r"(mbar), "r"(parity) : "memory");
}

// One-shot 32KB global->shared bulk copy (TMA path; no per-thread LDG/STS).
__device__ __forceinline__ void bulk_fill(uint16_t* sx, const void* gsrc,
                                          uint32_t mbar, uint32_t parity) {
    if (threadIdx.x == 0) {
        asm volatile("mbarrier.arrive.expect_tx.shared::cta.b64 _, [%0], %1;"
                     :: "r"(mbar), "r"(32768u) : "memory");
        uint32_t dst = smem_u32(sx + 8);
        asm volatile(
            "cp.async.bulk.shared::cluster.global.mbarrier::complete_tx::bytes "
            "[%0], [%1], %2, [%3];"
            :: "r"(dst), "l"(gsrc), "r"(32768u), "r"(mbar) : "memory");
    }
    if (threadIdx.x < 8) sx[threadIdx.x] = 0;   // slots 0..7 (idx==-1 -> slot 7)
    mbar_wait(mbar, parity);
    __syncthreads();
}

// Software grid barrier (sense-reversal; self-resetting -> graph-replay-safe).
__device__ __forceinline__ void grid_barrier() {
    __threadfence();
    __syncthreads();
    if (threadIdx.x == 0) {
        unsigned gen = *(volatile unsigned*)&g_gen;
        if (atomicAdd(&g_count, 1u) == NB - 1u) {
            atomicExch(&g_count, 0u);
            __threadfence();
            atomicAdd(&g_gen, 1u);
        } else {
            while (*(volatile unsigned*)&g_gen == gen) { __nanosleep(32); }
        }
    }
    __syncthreads();
    __threadfence();
}

// Dual branch mask (proven): lane gets 4 int4 of branch A, 4 of branch B.
// Returns on ALL lanes: lo16 = branch_on batch mask of A, hi16 = of B.
__device__ __forceinline__ uint32_t branch_mask_dual(
    const int4* A, const int4* E, const uint16_t* __restrict__ sx) {
    int4 a0 = A[0], a1 = A[1], a2 = A[2], a3 = A[3];
    int4 e0 = E[0], e1 = E[1], e2 = E[2], e3 = E[3];
#define LK(v) ((uint32_t)sx[(v) + 8])
    uint32_t m0 = LK(a0.x) | (LK(e0.x) << 16), m1 = LK(a0.y) | (LK(e0.y) << 16);
    uint32_t m2 = LK(a0.z) | (LK(e0.z) << 16), m3 = LK(a0.w) | (LK(e0.w) << 16);
    uint32_t m4 = LK(a1.x) | (LK(e1.x) << 16), m5 = LK(a1.y) | (LK(e1.y) << 16);
    uint32_t m6 = LK(a1.z) | (LK(e1.z) << 16), m7 = LK(a1.w) | (LK(e1.w) << 16);
    uint32_t m8 = LK(a2.x) | (LK(e2.x) << 16), m9 = LK(a2.y) | (LK(e2.y) << 16);
    uint32_t mA = LK(a2.z) | (LK(e2.z) << 16), mB = LK(a2.w) | (LK(e2.w) << 16);
    uint32_t mC = LK(a3.x) | (LK(e3.x) << 16), mD = LK(a3.y) | (LK(e3.y) << 16);
    uint32_t mE = LK(a3.z) | (LK(e3.z) << 16), mF = LK(a3.w) | (LK(e3.w) << 16);
#undef LK

    uint32_t s1 = m0 ^ m1 ^ m2, c1 = maj3(m0, m1, m2);
    uint32_t s2 = m3 ^ m4 ^ m5, c2 = maj3(m3, m4, m5);
    uint32_t s3 = s1 ^ s2 ^ m6, c3 = maj3(s1, s2, m6);
    uint32_t a1s = s3 ^ m7,      c4 = s3 & m7;
    uint32_t s4 = c1 ^ c2 ^ c3, c5 = maj3(c1, c2, c3);
    uint32_t a2s = s4 ^ c4,      c6 = s4 & c4;
    uint32_t a4s = c5 ^ c6,      a8s = c5 & c6;
    uint32_t u1 = m8 ^ m9 ^ mA, e1c = maj3(m8, m9, mA);
    uint32_t u2 = mB ^ mC ^ mD, e2c = maj3(mB, mC, mD);
    uint32_t u3 = u1 ^ u2 ^ mE, e3c = maj3(u1, u2, mE);
    uint32_t b1s = u3 ^ mF,      e4c = u3 & mF;
    uint32_t u4 = e1c ^ e2c ^ e3c, e5c = maj3(e1c, e2c, e3c);
    uint32_t b2s = u4 ^ e4c,       e6c = u4 & e4c;
    uint32_t b4s = e5c ^ e6c,      b8s = e5c & e6c;

    uint32_t k  = a1s & b1s;
    uint32_t v0 = a1s ^ b1s;
    uint32_t v1 = a2s ^ b2s ^ k;  k = maj3(a2s, b2s, k);
    uint32_t v2 = a4s ^ b4s ^ k;  k = maj3(a4s, b4s, k);
    uint32_t v3 = a8s ^ b8s ^ k;
    uint32_t v4 = maj3(a8s, b8s, k);

    uint32_t r0 = SHFLX(v0, 1), r1 = SHFLX(v1, 1), r2 = SHFLX(v2, 1),
             r3 = SHFLX(v3, 1), r4 = SHFLX(v4, 1);
    k = v0 & r0;
    uint32_t t0 = v0 ^ r0;
    uint32_t t1 = v1 ^ r1 ^ k;  k = maj3(v1, r1, k);
    uint32_t t2 = v2 ^ r2 ^ k;  k = maj3(v2, r2, k);
    uint32_t t3 = v3 ^ r3 ^ k;  k = maj3(v3, r3, k);
    uint32_t t4 = v4 ^ r4 ^ k;
    uint32_t t5 = maj3(v4, r4, k);

    r0 = SHFLX(t0, 2); r1 = SHFLX(t1, 2); r2 = SHFLX(t2, 2); r3 = SHFLX(t3, 2);
    r4 = SHFLX(t4, 2); uint32_t r5 = SHFLX(t5, 2);
    k = t0 & r0;
    k = maj3(t1, r1, k);
    k = maj3(t2, r2, k);
    k = maj3(t3, r3, k);
    uint32_t segmask = t4 | r4 | t5 | r5 | k;

    uint32_t p  = SHFLX(segmask, 4);
    uint32_t c0 = segmask ^ p, cc1 = segmask & p;
    uint32_t q0 = SHFLX(c0, 8), q1 = SHFLX(cc1, 8);
    k = c0 & q0;
    uint32_t f0 = c0 ^ q0;
    uint32_t f1 = cc1 ^ q1 ^ k;
    uint32_t f2 = maj3(cc1, q1, k);
    uint32_t h0 = SHFLX(f0, 16), h1 = SHFLX(f1, 16), h2 = SHFLX(f2, 16);
    k = f0 & h0;
    uint32_t k2 = maj3(f1, h1, k);
    return f2 | h2 | k2;
}

// Pack x (16 x 16384 floats of {0,1}) into per-position 16-bit batch masks.
__global__ void __launch_bounds__(256) k_pack(const float* __restrict__ x) {
    int j = blockIdx.x * 256 + threadIdx.x;
    float v[16];
#pragma unroll
    for (int b = 0; b < 16; b++) v[b] = x[b * 16384 + j];
    uint32_t m = 0;
#pragma unroll
    for (int b = 0; b < 16; b++)
        m |= (v[b] != 0.0f) ? (1u << b) : 0u;
    g_xbits[j] = (uint16_t)m;
    cudaTriggerProgrammaticLaunchCompletion();
}

// Fused layers: 256 blocks x 8 warps.
// Layer1: warp = 4 dual-pairs; DEPTH-2 software pipeline (two rotating
// register buffers) keeps 16 int4/lane in flight through every compute phase.
// Layer2: blocks 0..127, warp = 1 dual-pair, loads hoisted above grid barrier.
__global__ void __launch_bounds__(256, 2) k_main(const int* __restrict__ idx1,
                                                 const int* __restrict__ idx2,
                                                 float* __restrict__ out) {
    __shared__ __align__(16) uint16_t sx[16400];
    __shared__ __align__(8) uint64_t mbar[1];

    int tid = threadIdx.x;
    int w = tid >> 5, lane = tid & 31;
    int seg = lane >> 2, q = lane & 3;
    uint32_t mb = smem_u32(mbar);

    if (tid == 0) {
        asm volatile("mbarrier.init.shared::cta.b64 [%0], 1;" :: "r"(mb) : "memory");
    }

    int pair0 = (blockIdx.x * 8 + w) * 4;
    int laneoff = seg * 64 + q * 16;

    // ---- Hoist pairs 0 AND 1 above the PDL sync (16 int4/lane in flight) ----
    int4 A[2][4], E[2][4];
    {
        const int4* b0 = reinterpret_cast<const int4*>(idx1 + pair0 * 1024 + laneoff);
        const int4* b1 = reinterpret_cast<const int4*>(idx1 + (pair0 + 1) * 1024 + laneoff);
#pragma unroll
        for (int i = 0; i < 4; i++) A[0][i] = __ldcs(b0 + i);
#pragma unroll
        for (int i = 0; i < 4; i++) E[0][i] = __ldcs(b0 + 128 + i);
#pragma unroll
        for (int i = 0; i < 4; i++) A[1][i] = __ldcs(b1 + i);
#pragma unroll
        for (int i = 0; i < 4; i++) E[1][i] = __ldcs(b1 + 128 + i);
    }

    cudaGridDependencySynchronize();          // upstream: k_pack
    __syncthreads();                          // mbarrier init visible
    bulk_fill(sx, g_xbits, mb, 0);            // 32KB TMA fill, parity 0

    // ---- Layer 1: depth-2 pipeline over 4 dual-pairs ----
#pragma unroll
    for (int p = 0; p < 4; p++) {
        const int buf = p & 1;
        uint32_t ge = branch_mask_dual(A[buf], E[buf], sx);
        if (p + 2 < 4) {
            const int4* bn = reinterpret_cast<const int4*>(
                idx1 + (pair0 + p + 2) * 1024 + laneoff);
#pragma unroll
            for (int i = 0; i < 4; i++) A[buf][i] = __ldcs(bn + i);
#pragma unroll
            for (int i = 0; i < 4; i++) E[buf][i] = __ldcs(bn + 128 + i);
        }
        if (lane == 0)
            reinterpret_cast<uint32_t*>(g_act1)[pair0 + p] = ge;
    }

    // ---- Layer 2 loads hoisted ABOVE the grid barrier (independent of act1) ----
    bool active2 = blockIdx.x < 128;
    int pr = (blockIdx.x * 8 + w) * 2;        // even branch id = c*16 + br
    int c = pr >> 4, brA = pr & 15;
    if (active2) {
        const int4* baseA = reinterpret_cast<const int4*>(
            idx2 + (c * 1024 + brA * 8) * 64 + laneoff);
#pragma unroll
        for (int i = 0; i < 4; i++) A[0][i] = __ldcs(baseA + i);
#pragma unroll
        for (int i = 0; i < 4; i++) E[0][i] = __ldcs(baseA + 128 + i);
    }

    grid_barrier();                           // all act1 written & visible

    if (!active2) return;
    bulk_fill(sx, g_act1, mb, 1);             // parity 1 (second use of mbar)

    uint32_t ge4 = branch_mask_dual(A[0], E[0], sx);
    // lanes 0..15 -> batches of branch A; 16..31 -> batches of branch B
    int batch = lane & 15;
    int br = brA + (lane >> 4);
    out[(batch * 128 + c) * 16 + br] = ((ge4 >> lane) & 1u) ? 1.0f : 0.0f;
}

extern "C" void kernel_launch(void* const* d_in, const int* in_sizes, int n_in,
                              void* d_out, int out_size) {
    const float* x = nullptr;
    const int* idxA = nullptr;
    const int* idxB = nullptr;
    for (int i = 0; i < n_in; i++) {
        if (in_sizes[i] == 262144 && !x) {
            x = (const float*)d_in[i];
        } else if (!idxA) {
            idxA = (const int*)d_in[i];
        } else if (!idxB) {
            idxB = (const int*)d_in[i];
        }
    }
    if (!x) { x = (const float*)d_in[0]; idxA = (const int*)d_in[1]; idxB = (const int*)d_in[2]; }

    float* out = (float*)d_out;   // (16, 128, 16) float32

    k_pack<<<64, 256>>>(const_cast<float*>(x));

    cudaLaunchAttribute attr[1];
    attr[0].id = cudaLaunchAttributeProgrammaticStreamSerialization;
    attr[0].val.programmaticStreamSerializationAllowed = 1;

    cudaLaunchConfig_t cfg = {};
    cfg.gridDim = dim3(NB, 1, 1);
    cfg.blockDim = dim3(256, 1, 1);
    cfg.dynamicSmemBytes = 0;
    cfg.stream = 0;
    cfg.attrs = attr;
    cfg.numAttrs = 1;
    cudaLaunchKernelEx(&cfg, k_main, idxA, idxB, out);
}

// round 16
// speedup vs baseline: 1.2393x; 1.1047x over previous
#include <cuda_runtime.h>
#include <cuda_bf16.h>
#include <cstdint>

// Constants: B=16, C=128, T=8, BR=16, S=8, SY=64, INPUT_SIZE=16384, C*T*BR=16384
// seg_on = (count>=16 of 64), branch_on = (count>=4 of 8)
// Output = layer2 branch_on at t==0 -> (16,128,16) float32

__device__ __align__(16) uint16_t g_xbits[16384];
__device__ __align__(16) uint16_t g_act1[16384];

__device__ __forceinline__ uint32_t maj3(uint32_t a, uint32_t b, uint32_t c) {
    return (a & b) | (a & c) | (b & c);
}

#define SHFLX(v, m) __shfl_xor_sync(0xffffffffu, (v), (m))

__device__ __forceinline__ uint32_t smem_u32(const void* p) {
    uint32_t a;
    asm("{ .reg .u64 t; cvta.to.shared.u64 t, %1; cvt.u32.u64 %0, t; }"
        : "=r"(a) : "l"(p));
    return a;
}

__device__ __forceinline__ void mbar_wait(uint32_t mbar, uint32_t parity) {
    asm volatile(
        "{\n\t"
        ".reg .pred P;\n\t"
        "W_%=:\n\t"
        "mbarrier.try_wait.parity.shared::cta.b64 P, [%0], %1;\n\t"
        "@!P bra W_%=;\n\t"
        "}" :: "r"(mbar), "r"(parity) : "memory");
}

// One-shot 32KB global->shared bulk copy (TMA path; no per-thread LDG/STS).
// Caller must have run an mbarrier.init (tid 0) + __syncthreads() beforehand.
__device__ __forceinline__ void bulk_fill(uint16_t* sx, const void* gsrc,
                                          uint32_t mbar) {
    if (threadIdx.x == 0) {
        asm volatile("mbarrier.arrive.expect_tx.shared::cta.b64 _, [%0], %1;"
                     :: "r"(mbar), "r"(32768u) : "memory");
        uint32_t dst = smem_u32(sx + 8);
        asm volatile(
            "cp.async.bulk.shared::cluster.global.mbarrier::complete_tx::bytes "
            "[%0], [%1], %2, [%3];"
            :: "r"(dst), "l"(gsrc), "r"(32768u), "r"(mbar) : "memory");
    }
    if (threadIdx.x < 8) sx[threadIdx.x] = 0;   // slots 0..7 (idx==-1 -> slot 7)
    mbar_wait(mbar, 0);
    __syncthreads();
}

// Dual branch mask (proven): lane gets 4 int4 of branch A, 4 of branch B.
// Lane L owns segment L>>2, quarter L&3. Returns on ALL lanes:
// lo16 = branch_on batch mask of A, hi16 = of B.
__device__ __forceinline__ uint32_t branch_mask_dual(
    const int4* A, const int4* E, const uint16_t* __restrict__ sx) {
    int4 a0 = A[0], a1 = A[1], a2 = A[2], a3 = A[3];
    int4 e0 = E[0], e1 = E[1], e2 = E[2], e3 = E[3];
#define LK(v) ((uint32_t)sx[(v) + 8])
    uint32_t m0 = LK(a0.x) | (LK(e0.x) << 16), m1 = LK(a0.y) | (LK(e0.y) << 16);
    uint32_t m2 = LK(a0.z) | (LK(e0.z) << 16), m3 = LK(a0.w) | (LK(e0.w) << 16);
    uint32_t m4 = LK(a1.x) | (LK(e1.x) << 16), m5 = LK(a1.y) | (LK(e1.y) << 16);
    uint32_t m6 = LK(a1.z) | (LK(e1.z) << 16), m7 = LK(a1.w) | (LK(e1.w) << 16);
    uint32_t m8 = LK(a2.x) | (LK(e2.x) << 16), m9 = LK(a2.y) | (LK(e2.y) << 16);
    uint32_t mA = LK(a2.z) | (LK(e2.z) << 16), mB = LK(a2.w) | (LK(e2.w) << 16);
    uint32_t mC = LK(a3.x) | (LK(e3.x) << 16), mD = LK(a3.y) | (LK(e3.y) << 16);
    uint32_t mE = LK(a3.z) | (LK(e3.z) << 16), mF = LK(a3.w) | (LK(e3.w) << 16);
#undef LK

    uint32_t s1 = m0 ^ m1 ^ m2, c1 = maj3(m0, m1, m2);
    uint32_t s2 = m3 ^ m4 ^ m5, c2 = maj3(m3, m4, m5);
    uint32_t s3 = s1 ^ s2 ^ m6, c3 = maj3(s1, s2, m6);
    uint32_t a1s = s3 ^ m7,      c4 = s3 & m7;
    uint32_t s4 = c1 ^ c2 ^ c3, c5 = maj3(c1, c2, c3);
    uint32_t a2s = s4 ^ c4,      c6 = s4 & c4;
    uint32_t a4s = c5 ^ c6,      a8s = c5 & c6;
    uint32_t u1 = m8 ^ m9 ^ mA, e1c = maj3(m8, m9, mA);
    uint32_t u2 = mB ^ mC ^ mD, e2c = maj3(mB, mC, mD);
    uint32_t u3 = u1 ^ u2 ^ mE, e3c = maj3(u1, u2, mE);
    uint32_t b1s = u3 ^ mF,      e4c = u3 & mF;
    uint32_t u4 = e1c ^ e2c ^ e3c, e5c = maj3(e1c, e2c, e3c);
    uint32_t b2s = u4 ^ e4c,       e6c = u4 & e4c;
    uint32_t b4s = e5c ^ e6c,      b8s = e5c & e6c;

    uint32_t k  = a1s & b1s;
    uint32_t v0 = a1s ^ b1s;
    uint32_t v1 = a2s ^ b2s ^ k;  k = maj3(a2s, b2s, k);
    uint32_t v2 = a4s ^ b4s ^ k;  k = maj3(a4s, b4s, k);
    uint32_t v3 = a8s ^ b8s ^ k;
    uint32_t v4 = maj3(a8s, b8s, k);

    uint32_t r0 = SHFLX(v0, 1), r1 = SHFLX(v1, 1), r2 = SHFLX(v2, 1),
             r3 = SHFLX(v3, 1), r4 = SHFLX(v4, 1);
    k = v0 & r0;
    uint32_t t0 = v0 ^ r0;
    uint32_t t1 = v1 ^ r1 ^ k;  k = maj3(v1, r1, k);
    uint32_t t2 = v2 ^ r2 ^ k;  k = maj3(v2, r2, k);
    uint32_t t3 = v3 ^ r3 ^ k;  k = maj3(v3, r3, k);
    uint32_t t4 = v4 ^ r4 ^ k;
    uint32_t t5 = maj3(v4, r4, k);

    r0 = SHFLX(t0, 2); r1 = SHFLX(t1, 2); r2 = SHFLX(t2, 2); r3 = SHFLX(t3, 2);
    r4 = SHFLX(t4, 2); uint32_t r5 = SHFLX(t5, 2);
    k = t0 & r0;
    k = maj3(t1, r1, k);
    k = maj3(t2, r2, k);
    k = maj3(t3, r3, k);
    uint32_t segmask = t4 | r4 | t5 | r5 | k;

    uint32_t p  = SHFLX(segmask, 4);
    uint32_t c0 = segmask ^ p, cc1 = segmask & p;
    uint32_t q0 = SHFLX(c0, 8), q1 = SHFLX(cc1, 8);
    k = c0 & q0;
    uint32_t f0 = c0 ^ q0;
    uint32_t f1 = cc1 ^ q1 ^ k;
    uint32_t f2 = maj3(cc1, q1, k);
    uint32_t h0 = SHFLX(f0, 16), h1 = SHFLX(f1, 16), h2 = SHFLX(f2, 16);
    k = f0 & h0;
    uint32_t k2 = maj3(f1, h1, k);
    return f2 | h2 | k2;
}

// Pack x (16 x 16384 floats of {0,1}) into per-position 16-bit batch masks.
__global__ void __launch_bounds__(256) k_pack(const float* __restrict__ x) {
    int j = blockIdx.x * 256 + threadIdx.x;
    float v[16];
#pragma unroll
    for (int b = 0; b < 16; b++) v[b] = x[b * 16384 + j];
    uint32_t m = 0;
#pragma unroll
    for (int b = 0; b < 16; b++)
        m |= (v[b] != 0.0f) ? (1u << b) : 0u;
    g_xbits[j] = (uint16_t)m;
    cudaTriggerProgrammaticLaunchCompletion();
}

// Layer 1: 1024 blocks x 8 warps; warp = ONE dual-pair (8192 pairs).
// Short ~450-cycle chain per warp; idx loads hoisted above the PDL sync;
// table fill via one 32KB TMA bulk copy (L2-resident source).
__global__ void __launch_bounds__(256) k_l1(const int* __restrict__ idx1) {
    __shared__ __align__(16) uint16_t sx[16400];
    __shared__ __align__(8) uint64_t mbar[1];

    int tid = threadIdx.x;
    int w = tid >> 5, lane = tid & 31;
    int seg = lane >> 2, q = lane & 3;
    uint32_t mb = smem_u32(mbar);
    if (tid == 0)
        asm volatile("mbarrier.init.shared::cta.b64 [%0], 1;" :: "r"(mb) : "memory");

    int pair = blockIdx.x * 8 + w;               // 0..8191
    int laneoff = seg * 64 + q * 16;
    const int4* bA = reinterpret_cast<const int4*>(idx1 + pair * 1024 + laneoff);

    int4 A[4], E[4];
#pragma unroll
    for (int i = 0; i < 4; i++) A[i] = __ldcs(bA + i);
#pragma unroll
    for (int i = 0; i < 4; i++) E[i] = __ldcs(bA + 128 + i);

    cudaGridDependencySynchronize();             // upstream: k_pack
    __syncthreads();                             // mbarrier init visible
    bulk_fill(sx, g_xbits, mb);

    uint32_t ge = branch_mask_dual(A, E, sx);
    if (lane == 0)
        reinterpret_cast<uint32_t*>(g_act1)[pair] = ge;
    cudaTriggerProgrammaticLaunchCompletion();
}

// Layer 2 (t==0 only): 128 blocks x 8 warps; warp = one (c,br) dual-pair.
__global__ void __launch_bounds__(256) k_l2(const int* __restrict__ idx2,
                                            float* __restrict__ out) {
    __shared__ __align__(16) uint16_t sx[16400];
    __shared__ __align__(8) uint64_t mbar[1];

    int tid = threadIdx.x;
    int w = tid >> 5, lane = tid & 31;
    int seg = lane >> 2, q = lane & 3;
    uint32_t mb = smem_u32(mbar);
    if (tid == 0)
        asm volatile("mbarrier.init.shared::cta.b64 [%0], 1;" :: "r"(mb) : "memory");

    int pr = (blockIdx.x * 8 + w) * 2;           // even branch id = c*16 + br
    int c = pr >> 4, brA = pr & 15;
    int laneoff = seg * 64 + q * 16;
    const int4* baseA = reinterpret_cast<const int4*>(
        idx2 + (c * 1024 + brA * 8) * 64 + laneoff);

    int4 A[4], E[4];
#pragma unroll
    for (int i = 0; i < 4; i++) A[i] = __ldcs(baseA + i);
#pragma unroll
    for (int i = 0; i < 4; i++) E[i] = __ldcs(baseA + 128 + i);

    cudaGridDependencySynchronize();             // upstream: k_l1
    __syncthreads();
    bulk_fill(sx, g_act1, mb);

    uint32_t ge4 = branch_mask_dual(A, E, sx);
    // lanes 0..15 -> batches of branch A; 16..31 -> batches of branch B
    int batch = lane & 15;
    int br = brA + (lane >> 4);
    out[(batch * 128 + c) * 16 + br] = ((ge4 >> lane) & 1u) ? 1.0f : 0.0f;
}

extern "C" void kernel_launch(void* const* d_in, const int* in_sizes, int n_in,
                              void* d_out, int out_size) {
    const float* x = nullptr;
    const int* idxA = nullptr;
    const int* idxB = nullptr;
    for (int i = 0; i < n_in; i++) {
        if (in_sizes[i] == 262144 && !x) {
            x = (const float*)d_in[i];
        } else if (!idxA) {
            idxA = (const int*)d_in[i];
        } else if (!idxB) {
            idxB = (const int*)d_in[i];
        }
    }
    if (!x) { x = (const float*)d_in[0]; idxA = (const int*)d_in[1]; idxB = (const int*)d_in[2]; }

    float* out = (float*)d_out;   // (16, 128, 16) float32

    k_pack<<<64, 256>>>(const_cast<float*>(x));

    cudaLaunchAttribute attr[1];
    attr[0].id = cudaLaunchAttributeProgrammaticStreamSerialization;
    attr[0].val.programmaticStreamSerializationAllowed = 1;

    {
        cudaLaunchConfig_t cfg = {};
        cfg.gridDim = dim3(1024, 1, 1);
        cfg.blockDim = dim3(256, 1, 1);
        cfg.dynamicSmemBytes = 0;
        cfg.stream = 0;
        cfg.attrs = attr;
        cfg.numAttrs = 1;
        cudaLaunchKernelEx(&cfg, k_l1, idxA);
    }
    {
        cudaLaunchConfig_t cfg = {};
        cfg.gridDim = dim3(128, 1, 1);
        cfg.blockDim = dim3(256, 1, 1);
        cfg.dynamicSmemBytes = 0;
        cfg.stream = 0;
        cfg.attrs = attr;
        cfg.numAttrs = 1;
        cudaLaunchKernelEx(&cfg, k_l2, idxB, out);
    }
}